// round 11
// baseline (speedup 1.0000x reference)
#include <cuda_runtime.h>

// Problem constants
#define BATCH 4
#define DD 128
#define HH 128
#define WW 128
#define SLICE (HH*WW)          // 16384
#define VOL   (DD*HH*WW)       // 2097152
#define VTOT  (BATCH*VOL)      // 8388608
#define WS 11
#define RAD 5

#define C1F 1.0e-4f            // 0.01^2
#define C2F 9.0e-4f            // 0.03^2

// Separable 1-D Gaussian, window 11, sigma 1.5, normalized (compile-time).
__device__ constexpr float WL[6] = {
    0.00102838f, 0.00759876f, 0.03600077f,
    0.10936070f, 0.21300554f, 0.26601172f
};

// Packed intermediate: float4 = (mu1, mu2, E[x^2]+E[y^2], E[xy]) per voxel.
__device__ float4 g_m4[VTOT];
__device__ double g_acc;
__device__ unsigned g_cnt;

// ---------------------------------------------------------------------------
// Packed f32x2 helpers (Blackwell fma.rn.f32x2 / mul.rn.f32x2)
// ---------------------------------------------------------------------------
__device__ __forceinline__ float2 ffma2(float2 a, float2 b, float2 c) {
    float2 d;
    asm("fma.rn.f32x2 %0, %1, %2, %3;"
        : "=l"(reinterpret_cast<unsigned long long&>(d))
        : "l"(reinterpret_cast<unsigned long long&>(a)),
          "l"(reinterpret_cast<unsigned long long&>(b)),
          "l"(reinterpret_cast<unsigned long long&>(c)));
    return d;
}
__device__ __forceinline__ float2 fmul2(float2 a, float2 b) {
    float2 d;
    asm("mul.rn.f32x2 %0, %1, %2;"
        : "=l"(reinterpret_cast<unsigned long long&>(d))
        : "l"(reinterpret_cast<unsigned long long&>(a)),
          "l"(reinterpret_cast<unsigned long long&>(b)));
    return d;
}

// ---------------------------------------------------------------------------
// reset: zero accumulator (graph-replay safe; ordered before K2 in stream).
// ---------------------------------------------------------------------------
__global__ void reset_kernel() { g_acc = 0.0; }

// ---------------------------------------------------------------------------
// K1: y-marching x+y conv, 2 rows/step, prefetch distance 2.
// Block = 128 threads = 4 autonomous warps, each owning a 32-wide x-strip
// with a private 42-entry smem row buffer -> __syncwarp only, no BAR.SYNC.
// Grid = (yhalf=2, z=128, b=4) = 1024 blocks.
// Ring of 12 x-convolved rows (packed fields) in registers.
// ---------------------------------------------------------------------------
#define SWID 44    // padded per-warp row width (42 used)

__device__ __forceinline__ float4 fetch_pair(
    const float* __restrict__ img1, const float* __restrict__ img2,
    size_t base, int r0, int gx)
{
    bool okx = (unsigned)gx < WW;
    bool ok0 = okx && (unsigned)r0 < HH;
    bool ok1 = okx && (unsigned)(r0 + 1) < HH;
    size_t i0 = base + (size_t)(ok0 ? r0 : 0) * WW + (okx ? gx : 0);
    size_t i1 = base + (size_t)(ok1 ? (r0 + 1) : 0) * WW + (okx ? gx : 0);
    float4 f;
    f.x = ok0 ? __ldg(img1 + i0) : 0.f;
    f.y = ok0 ? __ldg(img2 + i0) : 0.f;
    f.z = ok1 ? __ldg(img1 + i1) : 0.f;
    f.w = ok1 ? __ldg(img2 + i1) : 0.f;
    return f;
}

__global__ __launch_bounds__(128, 4) void conv_xy_kernel(
    const float* __restrict__ img1, const float* __restrict__ img2)
{
    __shared__ float4 sAB[4][2][SWID];   // [warp][buffer][idx]: (a0,b0,a1,b1)

    const int tid  = threadIdx.x;
    const int wid  = tid >> 5;
    const int lane = tid & 31;
    const int yh = blockIdx.x;           // 0 or 1
    const int z  = blockIdx.y;
    const int b  = blockIdx.z;
    const int y0 = yh * 64;
    const int wx0 = wid * 32;            // this warp's output-strip start x
    const size_t base = ((size_t)b * DD + z) * SLICE;

    float2 w2s[6];
    #pragma unroll
    for (int t = 0; t < 6; ++t) w2s[t] = make_float2(WL[t], WL[t]);
    #define W2(t) w2s[((t) < 6) ? (t) : (10 - (t))]

    // Ring of 12 x-convolved rows: rMU = (mu1,mu2), rCQ = (csum, c12).
    float2 rMU[12], rCQ[12];

    // Prefetch steps 0 and 1. Each warp covers strip idx 0..41:
    // main slot idx = lane (gx = wx0-5+lane), halo slot idx = 32+lane (lane<10).
    float4 fm[2], fh[2];
    fm[0] = fetch_pair(img1, img2, base, y0 - 5, wx0 - 5 + lane);
    fh[0] = (lane < 10) ? fetch_pair(img1, img2, base, y0 - 5, wx0 + 27 + lane)
                        : make_float4(0.f, 0.f, 0.f, 0.f);
    fm[1] = fetch_pair(img1, img2, base, y0 - 3, wx0 - 5 + lane);
    fh[1] = (lane < 10) ? fetch_pair(img1, img2, base, y0 - 3, wx0 + 27 + lane)
                        : make_float4(0.f, 0.f, 0.f, 0.f);

    // One step: publish f*[j&1], prefetch step k+2, x-conv -> slots (2j,2j+1),
    // y-conv -> outputs y0+2k-10, y0+2k-9 (when k >= 5).
    #define STEP(k, j, DO_FETCH)                                              \
    {                                                                         \
        float4* rowbuf = sAB[wid][(j) & 1];                                   \
        rowbuf[lane] = fm[(j) & 1];                                           \
        if (lane < 10) rowbuf[32 + lane] = fh[(j) & 1];                       \
        __syncwarp();                                                         \
        if (DO_FETCH) {                                                       \
            fm[(j) & 1] = fetch_pair(img1, img2, base,                        \
                                     y0 + 2 * (k) - 1, wx0 - 5 + lane);       \
            fh[(j) & 1] = (lane < 10)                                         \
                ? fetch_pair(img1, img2, base,                                \
                             y0 + 2 * (k) - 1, wx0 + 27 + lane)               \
                : make_float4(0.f, 0.f, 0.f, 0.f);                            \
        }                                                                     \
        float2 xmu0 = make_float2(0.f, 0.f), xcv0 = make_float2(0.f, 0.f);    \
        float2 xmu1 = make_float2(0.f, 0.f), xcv1 = make_float2(0.f, 0.f);    \
        float2 xp01 = make_float2(0.f, 0.f);                                  \
        _Pragma("unroll")                                                     \
        for (int t = 0; t < WS; ++t) {                                        \
            float2 wv = W2(t);                                                \
            float4 v4 = rowbuf[lane + t];                                     \
            float2 ab0 = make_float2(v4.x, v4.y);                             \
            float2 ab1 = make_float2(v4.z, v4.w);                             \
            float2 sq0 = fmul2(ab0, ab0);                                     \
            float2 sq1 = fmul2(ab1, ab1);                                     \
            float2 pp  = make_float2(v4.x * v4.y, v4.z * v4.w);               \
            xmu0 = ffma2(wv, ab0, xmu0);                                      \
            xcv0 = ffma2(wv, sq0, xcv0);                                      \
            xmu1 = ffma2(wv, ab1, xmu1);                                      \
            xcv1 = ffma2(wv, sq1, xcv1);                                      \
            xp01 = ffma2(wv, pp, xp01);                                       \
        }                                                                     \
        rMU[(2 * (j)) % 12]     = xmu0;                                       \
        rCQ[(2 * (j)) % 12]     = make_float2(xcv0.x + xcv0.y, xp01.x);       \
        rMU[(2 * (j) + 1) % 12] = xmu1;                                       \
        rCQ[(2 * (j) + 1) % 12] = make_float2(xcv1.x + xcv1.y, xp01.y);       \
        if ((k) >= 5) {                                                       \
            float2 amu0 = make_float2(0.f, 0.f), acq0 = make_float2(0.f, 0.f);\
            float2 amu1 = make_float2(0.f, 0.f), acq1 = make_float2(0.f, 0.f);\
            _Pragma("unroll")                                                 \
            for (int t = 0; t < WS; ++t) {                                    \
                float2 wv = W2(t);                                            \
                const int s0 = (2 * (j) + t + 2) % 12;                        \
                const int s1 = (2 * (j) + t + 3) % 12;                        \
                amu0 = ffma2(wv, rMU[s0], amu0);                              \
                acq0 = ffma2(wv, rCQ[s0], acq0);                              \
                amu1 = ffma2(wv, rMU[s1], amu1);                              \
                acq1 = ffma2(wv, rCQ[s1], acq1);                              \
            }                                                                 \
            size_t o0 = base + (size_t)(y0 + 2 * (k) - 10) * WW + wx0 + lane; \
            g_m4[o0]      = make_float4(amu0.x, amu0.y, acq0.x, acq0.y);      \
            g_m4[o0 + WW] = make_float4(amu1.x, amu1.y, acq1.x, acq1.y);      \
        }                                                                     \
    }

    // Main: 36 steps (k = 6*ko + j), then 1 epilogue step (k=36, phase j=0).
    for (int ko = 0; ko < 6; ++ko) {
        #pragma unroll
        for (int j = 0; j < 6; ++j) {
            const int k = 6 * ko + j;
            STEP(k, j, true)
        }
    }
    STEP(36, 0, false)
    #undef STEP
    #undef W2
}

// ---------------------------------------------------------------------------
// K2: z-conv + SSIM + reduction + finalize. 64-z chunks: 1024 blocks x 128.
// Ring in registers (compile-time slots), depth-3 prefetch, LDG.128 loads.
// Loop = outer 2 x unrolled 33 (33 % 11 == 0, 33 % 3 == 0: all indices static).
// ---------------------------------------------------------------------------
__device__ __forceinline__ float4 load_plane(size_t col, int zz) {
    bool ok = (unsigned)zz < DD;
    size_t idx = col + (size_t)(ok ? zz : 0) * SLICE;
    float4 v = g_m4[idx];
    if (!ok) v = make_float4(0.f, 0.f, 0.f, 0.f);
    return v;
}

__global__ __launch_bounds__(128, 4) void conv_z_ssim_kernel(float* __restrict__ out)
{
    const int x  = threadIdx.x;
    const int zc = blockIdx.x;   // z-chunk of 64: 0..1
    const int y  = blockIdx.y;   // 0..127
    const int b  = blockIdx.z;   // 0..3
    const int z0 = zc * 64;
    const size_t col = (size_t)b * VOL + (size_t)y * WW + x;

    float2 w2s[6];
    #pragma unroll
    for (int t = 0; t < 6; ++t) w2s[t] = make_float2(WL[t], WL[t]);
    #define W2(t) w2s[((t) < 6) ? (t) : (10 - (t))]

    // Ring: slot s initially holds relative plane s-5.
    float4 ring[WS];
    #pragma unroll
    for (int s = 0; s < WS; ++s) ring[s] = load_plane(col, z0 + s - RAD);

    // Prefetch pipeline, depth 3: buffers hold relative planes 6..8.
    float4 pf[3];
    #pragma unroll
    for (int q = 0; q < 3; ++q) pf[q] = load_plane(col, z0 + RAD + 1 + q);

    float fsum = 0.f;
    for (int zo = 0; zo < 66; zo += 33) {    // zo in {0, 33}; 33%11=0, 33%3=0
        #pragma unroll
        for (int i = 0; i < 33; ++i) {       // oz = zo + i; indices use i only
            float2 mu = make_float2(0.f, 0.f), cq = make_float2(0.f, 0.f);
            #pragma unroll
            for (int s = 0; s < WS; ++s) {
                const int wi = ((s - i) % WS + WS) % WS;   // compile-time
                float2 wv = W2(wi);
                mu = ffma2(wv, make_float2(ring[s].x, ring[s].y), mu);
                cq = ffma2(wv, make_float2(ring[s].z, ring[s].w), cq);
            }
            float2 musq = fmul2(mu, mu);
            float mu12  = mu.x * mu.y;
            float svar  = cq.x - musq.x - musq.y;   // sigma1^2 + sigma2^2
            float s12   = cq.y - mu12;
            float num = (2.f * mu12 + C1F) * (2.f * s12 + C2F);
            float den = (musq.x + musq.y + C1F) * (svar + C2F);
            float v = __fdividef(num, den);
            if (zo + i < 64) fsum += v;

            // Insert prefetched plane oz+6 (slot i%11), refill with oz+9.
            ring[i % WS] = pf[i % 3];
            pf[i % 3] = load_plane(col, z0 + zo + i + RAD + 4);
        }
    }
    #undef W2

    // Block reduction -> global double accumulator -> last block finalizes.
    double dsum = (double)fsum;
    #pragma unroll
    for (int off = 16; off > 0; off >>= 1)
        dsum += __shfl_down_sync(0xffffffffu, dsum, off);

    __shared__ double ssm[4];
    int wid = threadIdx.x >> 5, lid = threadIdx.x & 31;
    if (lid == 0) ssm[wid] = dsum;
    __syncthreads();
    if (threadIdx.x == 0) {
        double tot = ssm[0] + ssm[1] + ssm[2] + ssm[3];
        atomicAdd(&g_acc, tot);
        __threadfence();
        unsigned done = atomicAdd(&g_cnt, 1u);
        if (done == (unsigned)(2 * HH * BATCH - 1)) {   // 1024 blocks
            out[0] = (float)(g_acc * (1.0 / (double)VTOT));
            g_cnt = 0;   // reset for next graph replay
        }
    }
}

// ---------------------------------------------------------------------------
extern "C" void kernel_launch(void* const* d_in, const int* in_sizes, int n_in,
                              void* d_out, int out_size) {
    (void)in_sizes; (void)n_in; (void)out_size;
    const float* img1 = (const float*)d_in[0];
    const float* img2 = (const float*)d_in[1];

    dim3 g1(2, DD, BATCH);                       // (2, 128, 4) = 1024 blocks
    conv_xy_kernel<<<g1, 128>>>(img1, img2);

    reset_kernel<<<1, 1>>>();

    dim3 g2(2, HH, BATCH);                       // (2, 128, 4) = 1024 blocks
    conv_z_ssim_kernel<<<g2, 128>>>((float*)d_out);
}

// round 12
// speedup vs baseline: 1.3236x; 1.3236x over previous
#include <cuda_runtime.h>

// Problem constants
#define BATCH 4
#define DD 128
#define HH 128
#define WW 128
#define SLICE (HH*WW)          // 16384
#define VOL   (DD*HH*WW)       // 2097152
#define VTOT  (BATCH*VOL)      // 8388608
#define WS 11
#define RAD 5

#define C1F 1.0e-4f            // 0.01^2
#define C2F 9.0e-4f            // 0.03^2

// Separable 1-D Gaussian, window 11, sigma 1.5, normalized (compile-time).
__device__ constexpr float WL[6] = {
    0.00102838f, 0.00759876f, 0.03600077f,
    0.10936070f, 0.21300554f, 0.26601172f
};

// Packed intermediate: float4 = (mu1, mu2, E[x^2]+E[y^2], E[xy]) per voxel.
__device__ float4 g_m4[VTOT];
__device__ double g_acc;
__device__ unsigned g_cnt;

// ---------------------------------------------------------------------------
// Packed f32x2 helpers (Blackwell fma.rn.f32x2 / mul.rn.f32x2)
// ---------------------------------------------------------------------------
__device__ __forceinline__ float2 ffma2(float2 a, float2 b, float2 c) {
    float2 d;
    asm("fma.rn.f32x2 %0, %1, %2, %3;"
        : "=l"(reinterpret_cast<unsigned long long&>(d))
        : "l"(reinterpret_cast<unsigned long long&>(a)),
          "l"(reinterpret_cast<unsigned long long&>(b)),
          "l"(reinterpret_cast<unsigned long long&>(c)));
    return d;
}
__device__ __forceinline__ float2 fmul2(float2 a, float2 b) {
    float2 d;
    asm("mul.rn.f32x2 %0, %1, %2;"
        : "=l"(reinterpret_cast<unsigned long long&>(d))
        : "l"(reinterpret_cast<unsigned long long&>(a)),
          "l"(reinterpret_cast<unsigned long long&>(b)));
    return d;
}

// ---------------------------------------------------------------------------
// reset: zero accumulator (graph-replay safe; ordered before K2 in stream).
// ---------------------------------------------------------------------------
__global__ void reset_kernel() { g_acc = 0.0; }

// ---------------------------------------------------------------------------
// K1: y-marching x+y conv, 2 rows/step, prefetch distance 2.
// Block = 128 threads = one full x row; handles a 64-row y-half.
// Grid = (yhalf=2, z=128, b=4) = 1024 blocks.
// Row pair published as one float4 (a0,b0,a1,b1): 11 LDS.128/step.
// Ring of 12 x-convolved rows (packed fields) in registers.
// All global addresses via running pointers (+= 2*WW per step) - no IMAD chains.
// ---------------------------------------------------------------------------
#define RWID 138   // 128 + 2*RAD

__device__ __forceinline__ float4 fetch_pair_p(
    const float* __restrict__ p1, const float* __restrict__ p2, int row)
{
    // Loads rows (row, row+1) at the pointers; predicated off out of range.
    bool ok0 = (unsigned)row < HH;
    bool ok1 = (unsigned)(row + 1) < HH;
    float4 f;
    f.x = ok0 ? __ldg(p1)      : 0.f;
    f.y = ok0 ? __ldg(p2)      : 0.f;
    f.z = ok1 ? __ldg(p1 + WW) : 0.f;
    f.w = ok1 ? __ldg(p2 + WW) : 0.f;
    return f;
}

__global__ __launch_bounds__(128, 4) void conv_xy_kernel(
    const float* __restrict__ img1, const float* __restrict__ img2)
{
    __shared__ float4 sAB[2][RWID];      // [buffer][x]: (a0,b0,a1,b1)

    const int x  = threadIdx.x;          // 0..127
    const int yh = blockIdx.x;           // 0 or 1
    const int z  = blockIdx.y;
    const int b  = blockIdx.z;
    const int y0 = yh * 64;
    const size_t base = ((size_t)b * DD + z) * SLICE;

    // Zero the x halos once (never overwritten afterwards).
    if (x < RAD) {
        #pragma unroll
        for (int u = 0; u < 2; ++u) {
            sAB[u][x]       = make_float4(0.f, 0.f, 0.f, 0.f);
            sAB[u][133 + x] = make_float4(0.f, 0.f, 0.f, 0.f);
        }
    }
    __syncthreads();

    float2 w2s[6];
    #pragma unroll
    for (int t = 0; t < 6; ++t) w2s[t] = make_float2(WL[t], WL[t]);
    #define W2(t) w2s[((t) < 6) ? (t) : (10 - (t))]

    // Ring of 12 x-convolved rows: rMU = (mu1,mu2), rCQ = (csum, c12).
    float2 rMU[12], rCQ[12];

    // Running state. At step k: fetch targets rows (y0+2k-1, y0+2k), store
    // targets rows (y0+2k-10, y0+2k-9). inRow tracks y0+2k-1.
    int inRow = y0 - 1;
    const float* p1  = img1 + base + (ptrdiff_t)inRow * WW + x;
    const float* p2  = img2 + base + (ptrdiff_t)inRow * WW + x;
    float4*      po  = g_m4 + base + (ptrdiff_t)(y0 - 10) * WW + x;

    // Prefetch steps 0 and 1 (rows y0-5..y0-2; real rows only for yh=1).
    float4 f[2];
    f[0] = fetch_pair_p(p1 - 4 * WW, p2 - 4 * WW, inRow - 4);
    f[1] = fetch_pair_p(p1 - 2 * WW, p2 - 2 * WW, inRow - 2);

    // One step: publish f[j&1], prefetch k+2, x-conv -> slots (2j, 2j+1),
    // y-conv -> store rows via po (when k >= 5). Pointers advance by 2*WW.
    #define STEP(k, j, DO_FETCH)                                              \
    {                                                                         \
        float4* rowbuf = sAB[(j) & 1];                                        \
        rowbuf[x + RAD] = f[(j) & 1];                                         \
        __syncthreads();                                                      \
        if (DO_FETCH) f[(j) & 1] = fetch_pair_p(p1, p2, inRow);               \
        float2 xmu0 = make_float2(0.f, 0.f), xcv0 = make_float2(0.f, 0.f);    \
        float2 xmu1 = make_float2(0.f, 0.f), xcv1 = make_float2(0.f, 0.f);    \
        float2 xp01 = make_float2(0.f, 0.f);                                  \
        _Pragma("unroll")                                                     \
        for (int t = 0; t < WS; ++t) {                                        \
            float2 wv = W2(t);                                                \
            float4 v4 = rowbuf[x + t];                                        \
            float2 ab0 = make_float2(v4.x, v4.y);                             \
            float2 ab1 = make_float2(v4.z, v4.w);                             \
            float2 sq0 = fmul2(ab0, ab0);                                     \
            float2 sq1 = fmul2(ab1, ab1);                                     \
            float2 pp  = make_float2(v4.x * v4.y, v4.z * v4.w);               \
            xmu0 = ffma2(wv, ab0, xmu0);                                      \
            xcv0 = ffma2(wv, sq0, xcv0);                                      \
            xmu1 = ffma2(wv, ab1, xmu1);                                      \
            xcv1 = ffma2(wv, sq1, xcv1);                                      \
            xp01 = ffma2(wv, pp, xp01);                                       \
        }                                                                     \
        rMU[(2 * (j)) % 12]     = xmu0;                                       \
        rCQ[(2 * (j)) % 12]     = make_float2(xcv0.x + xcv0.y, xp01.x);       \
        rMU[(2 * (j) + 1) % 12] = xmu1;                                       \
        rCQ[(2 * (j) + 1) % 12] = make_float2(xcv1.x + xcv1.y, xp01.y);       \
        if ((k) >= 5) {                                                       \
            float2 amu0 = make_float2(0.f, 0.f), acq0 = make_float2(0.f, 0.f);\
            float2 amu1 = make_float2(0.f, 0.f), acq1 = make_float2(0.f, 0.f);\
            _Pragma("unroll")                                                 \
            for (int t = 0; t < WS; ++t) {                                    \
                float2 wv = W2(t);                                            \
                const int s0 = (2 * (j) + t + 2) % 12;                        \
                const int s1 = (2 * (j) + t + 3) % 12;                        \
                amu0 = ffma2(wv, rMU[s0], amu0);                              \
                acq0 = ffma2(wv, rCQ[s0], acq0);                              \
                amu1 = ffma2(wv, rMU[s1], amu1);                              \
                acq1 = ffma2(wv, rCQ[s1], acq1);                              \
            }                                                                 \
            po[0]  = make_float4(amu0.x, amu0.y, acq0.x, acq0.y);             \
            po[WW] = make_float4(amu1.x, amu1.y, acq1.x, acq1.y);             \
        }                                                                     \
        p1 += 2 * WW; p2 += 2 * WW; po += 2 * WW; inRow += 2;                 \
    }

    // Main: 36 steps (k = 6*ko + j), then 1 epilogue step (k=36, phase j=0).
    for (int ko = 0; ko < 6; ++ko) {
        #pragma unroll
        for (int j = 0; j < 6; ++j) {
            const int k = 6 * ko + j;
            STEP(k, j, true)
        }
    }
    STEP(36, 0, false)
    #undef STEP
    #undef W2
}

// ---------------------------------------------------------------------------
// K2: z-conv + SSIM + reduction + finalize. 2048 blocks x 128 threads.
// Ring in registers (compile-time slots), depth-4 prefetch, LDG.128 loads.
// (Identical to the 97.4us round-10 version.)
// ---------------------------------------------------------------------------
__device__ __forceinline__ float4 load_plane(size_t col, int zz) {
    bool ok = (unsigned)zz < DD;
    size_t idx = col + (size_t)(ok ? zz : 0) * SLICE;
    float4 v = g_m4[idx];
    if (!ok) v = make_float4(0.f, 0.f, 0.f, 0.f);
    return v;
}

__global__ __launch_bounds__(128, 5) void conv_z_ssim_kernel(float* __restrict__ out)
{
    const int x  = threadIdx.x;
    const int zc = blockIdx.x;   // z-chunk of 32: 0..3
    const int y  = blockIdx.y;   // 0..127
    const int b  = blockIdx.z;   // 0..3
    const int z0 = zc * 32;
    const size_t col = (size_t)b * VOL + (size_t)y * WW + x;

    float2 w2s[6];
    #pragma unroll
    for (int t = 0; t < 6; ++t) w2s[t] = make_float2(WL[t], WL[t]);
    #define W2(t) w2s[((t) < 6) ? (t) : (10 - (t))]

    // Ring: slot s initially holds relative plane s-5.
    float4 ring[WS];
    #pragma unroll
    for (int s = 0; s < WS; ++s) ring[s] = load_plane(col, z0 + s - RAD);

    // Prefetch pipeline, depth 4: buffers hold relative planes 6..9.
    float4 pf[4];
    #pragma unroll
    for (int q = 0; q < 4; ++q) pf[q] = load_plane(col, z0 + RAD + 1 + q);

    float fsum = 0.f;
    #pragma unroll
    for (int oz = 0; oz < 33; ++oz) {   // 33 = 3*11 so slot math is compile-time
        float2 mu = make_float2(0.f, 0.f), cq = make_float2(0.f, 0.f);
        #pragma unroll
        for (int s = 0; s < WS; ++s) {
            const int wi = ((s - oz) % WS + WS) % WS;   // compile-time
            float2 wv = W2(wi);
            mu = ffma2(wv, make_float2(ring[s].x, ring[s].y), mu);
            cq = ffma2(wv, make_float2(ring[s].z, ring[s].w), cq);
        }
        float2 musq = fmul2(mu, mu);
        float mu12  = mu.x * mu.y;
        float svar  = cq.x - musq.x - musq.y;   // sigma1^2 + sigma2^2
        float s12   = cq.y - mu12;
        float num = (2.f * mu12 + C1F) * (2.f * s12 + C2F);
        float den = (musq.x + musq.y + C1F) * (svar + C2F);
        float v = __fdividef(num, den);
        if (oz < 32) fsum += v;

        // Insert prefetched plane oz+6 (slot oz%11), refill buffer with oz+10.
        ring[oz % WS] = pf[oz & 3];
        pf[oz & 3] = load_plane(col, z0 + oz + RAD + 5);
    }
    #undef W2

    // Block reduction -> global double accumulator -> last block finalizes.
    double dsum = (double)fsum;
    #pragma unroll
    for (int off = 16; off > 0; off >>= 1)
        dsum += __shfl_down_sync(0xffffffffu, dsum, off);

    __shared__ double ssm[4];
    int wid = threadIdx.x >> 5, lid = threadIdx.x & 31;
    if (lid == 0) ssm[wid] = dsum;
    __syncthreads();
    if (threadIdx.x == 0) {
        double tot = ssm[0] + ssm[1] + ssm[2] + ssm[3];
        atomicAdd(&g_acc, tot);
        __threadfence();
        unsigned done = atomicAdd(&g_cnt, 1u);
        if (done == (unsigned)(4 * HH * BATCH - 1)) {
            out[0] = (float)(g_acc * (1.0 / (double)VTOT));
            g_cnt = 0;   // reset for next graph replay
        }
    }
}

// ---------------------------------------------------------------------------
extern "C" void kernel_launch(void* const* d_in, const int* in_sizes, int n_in,
                              void* d_out, int out_size) {
    (void)in_sizes; (void)n_in; (void)out_size;
    const float* img1 = (const float*)d_in[0];
    const float* img2 = (const float*)d_in[1];

    dim3 g1(2, DD, BATCH);                       // (2, 128, 4) = 1024 blocks
    conv_xy_kernel<<<g1, 128>>>(img1, img2);

    reset_kernel<<<1, 1>>>();

    dim3 g2(DD / 32, HH, BATCH);                 // (4, 128, 4) = 2048 blocks
    conv_z_ssim_kernel<<<g2, 128>>>((float*)d_out);
}